// round 4
// baseline (speedup 1.0000x reference)
#include <cuda_runtime.h>

// ---------------------------------------------------------------------------
// Problem constants
// ---------------------------------------------------------------------------
#define D_MODEL  1024
#define D_INNER  2048
#define D_STATE  16
#define D_CONV   4
#define DT_RANK  64
#define BATCH    2
#define SEQLEN   2048
#define MROWS    (BATCH * SEQLEN)     // 4096
#define XDBL_N   (DT_RANK + 2 * D_STATE)  // 96

// ---------------------------------------------------------------------------
// Scratch (static device globals; no allocation allowed)
// ---------------------------------------------------------------------------
__device__ float g_xraw [MROWS * D_INNER];   // x (pre-conv), from even cols of xz
__device__ float g_zs   [MROWS * D_INNER];   // silu(z), from odd cols of xz
__device__ float g_xc   [MROWS * D_INNER];   // silu(conv(x)+bias)
__device__ float g_xdbl [MROWS * XDBL_N];    // x @ W_x
__device__ float g_delta[MROWS * D_INNER];   // softplus(dt)
__device__ float g_u    [MROWS * D_INNER];   // (y + x*D) * silu(z)
__device__ float g_Aneg [D_INNER * D_STATE]; // -exp(A_log)

// ---------------------------------------------------------------------------
// f32x2 packed-FMA helpers (Blackwell; ptxas never emits these from C++)
// ---------------------------------------------------------------------------
typedef unsigned long long ull;

__device__ __forceinline__ ull pk2(float x, float y) {
    ull r;
    asm("mov.b64 %0, {%1, %2};" : "=l"(r) : "f"(x), "f"(y));
    return r;
}
__device__ __forceinline__ void ffma2(ull& d, ull a, ull b) {
    asm("fma.rn.f32x2 %0, %1, %2, %0;" : "+l"(d) : "l"(a), "l"(b));
}
__device__ __forceinline__ float2 upk(ull v) {
    float2 r;
    asm("mov.b64 {%0, %1}, %2;" : "=f"(r.x), "=f"(r.y) : "l"(v));
    return r;
}

__device__ __forceinline__ float sigmoidf_(float v) {
    return 1.0f / (1.0f + __expf(-v));
}

// ---------------------------------------------------------------------------
// Generic tiled fp32 GEMM:  C = A(MxK, lda) @ B(KxN, ldb)
// BM=BN=128, BK=16, 256 threads, 8x8 per thread, f32x2 accumulation.
// Epilogues:
//   EPI 0: plain store (N-guarded)
//   EPI 1: xz split — even col -> C0 (x_raw), odd col -> C1 (silu -> zs)
//   EPI 2: +bias then softplus -> C0
// ---------------------------------------------------------------------------
#define BM 128
#define BN 128
#define BK 16
#define ASTRIDE 132   // padded, 16B-aligned rows (132*4 = 528 = 33*16)

template <int EPI>
__global__ __launch_bounds__(256)
void gemm_kernel(const float* __restrict__ A, const float* __restrict__ B,
                 float* __restrict__ C0, float* __restrict__ C1,
                 const float* __restrict__ bias,
                 int M, int N, int K, int lda, int ldb, int ldc)
{
    __shared__ float As[BK][ASTRIDE];
    __shared__ float Bs[BK][BN];

    const int tid = threadIdx.x;
    const int bx = blockIdx.x, by = blockIdx.y;
    const int tx = tid & 15;        // N direction (16)
    const int ty = tid >> 4;        // M direction (16)

    const int arow = tid >> 2;          // 0..63 (two passes of 64 rows)
    const int acol = (tid & 3) << 2;    // 0,4,8,12
    const int brow = tid >> 5;          // 0..7  (two passes of 8 rows)
    const int bcol = (tid & 31) << 2;   // 0..124

    const int row0 = by * BM;
    const int col0 = bx * BN;

    ull acc[8][4];
#pragma unroll
    for (int i = 0; i < 8; i++)
#pragma unroll
        for (int j = 0; j < 4; j++) acc[i][j] = 0ull;

    for (int k0 = 0; k0 < K; k0 += BK) {
        __syncthreads();
        // Load A tile (128 x 16), store transposed into As[k][m]
#pragma unroll
        for (int r = 0; r < 2; r++) {
            int m = arow + r * 64;
            float4 v = *(const float4*)&A[(long)(row0 + m) * lda + k0 + acol];
            As[acol + 0][m] = v.x;
            As[acol + 1][m] = v.y;
            As[acol + 2][m] = v.z;
            As[acol + 3][m] = v.w;
        }
        // Load B tile (16 x 128), natural layout, N-guarded
#pragma unroll
        for (int r = 0; r < 2; r++) {
            int kk = brow + r * 8;
            int n = col0 + bcol;
            float4 v = make_float4(0.f, 0.f, 0.f, 0.f);
            if (n < N) v = *(const float4*)&B[(long)(k0 + kk) * ldb + n];
            *(float4*)&Bs[kk][bcol] = v;
        }
        __syncthreads();

#pragma unroll
        for (int kk = 0; kk < BK; kk++) {
            float4 a0 = *(const float4*)&As[kk][ty * 8];
            float4 a1 = *(const float4*)&As[kk][ty * 8 + 4];
            float4 b0 = *(const float4*)&Bs[kk][tx * 8];
            float4 b1 = *(const float4*)&Bs[kk][tx * 8 + 4];
            ull bp[4];
            bp[0] = pk2(b0.x, b0.y);
            bp[1] = pk2(b0.z, b0.w);
            bp[2] = pk2(b1.x, b1.y);
            bp[3] = pk2(b1.z, b1.w);
            float av[8] = {a0.x, a0.y, a0.z, a0.w, a1.x, a1.y, a1.z, a1.w};
#pragma unroll
            for (int i = 0; i < 8; i++) {
                ull ad = pk2(av[i], av[i]);
#pragma unroll
                for (int j = 0; j < 4; j++) ffma2(acc[i][j], ad, bp[j]);
            }
        }
    }

    // Epilogue
#pragma unroll
    for (int i = 0; i < 8; i++) {
        int m = row0 + ty * 8 + i;
#pragma unroll
        for (int j = 0; j < 4; j++) {
            float2 v = upk(acc[i][j]);
            int n = col0 + tx * 8 + 2 * j;
            if (EPI == 0) {
                if (n < N)     C0[(long)m * ldc + n]     = v.x;
                if (n + 1 < N) C0[(long)m * ldc + n + 1] = v.y;
            } else if (EPI == 1) {
                // n even -> x, n+1 odd -> silu -> zs ; half-index = n/2
                int c = n >> 1;
                C0[(long)m * D_INNER + c] = v.x;
                C1[(long)m * D_INNER + c] = v.y * sigmoidf_(v.y);
            } else { // EPI == 2 : bias + softplus
                float a0 = v.x + bias[n];
                float a1 = v.y + bias[n + 1];
                a0 = (a0 > 20.f) ? a0 : log1pf(__expf(a0));
                a1 = (a1 > 20.f) ? a1 : log1pf(__expf(a1));
                C0[(long)m * ldc + n]     = a0;
                C0[(long)m * ldc + n + 1] = a1;
            }
        }
    }
}

// ---------------------------------------------------------------------------
// Depthwise causal-ish conv (SAME pad: lo=1, hi=2) + bias + silu, float4 wide
// ---------------------------------------------------------------------------
__global__ void conv_silu_kernel(const float* __restrict__ ck,
                                 const float* __restrict__ cb)
{
    int idx = blockIdx.x * blockDim.x + threadIdx.x;  // 4096*512 float4s
    if (idx >= MROWS * (D_INNER / 4)) return;
    int row = idx >> 9;            // 0..4095
    int d = (idx & 511) << 2;      // 0..2044 step 4
    int b = row >> 11;
    int l = row & (SEQLEN - 1);

    float4 acc = *(const float4*)&cb[d];
#pragma unroll
    for (int w = 0; w < D_CONV; w++) {
        int ls = l + w - 1;
        if (ls >= 0 && ls < SEQLEN) {
            float4 xv = *(const float4*)&g_xraw[((long)(b * SEQLEN + ls)) * D_INNER + d];
            float4 kv = *(const float4*)&ck[w * D_INNER + d];
            acc.x += xv.x * kv.x;
            acc.y += xv.y * kv.y;
            acc.z += xv.z * kv.z;
            acc.w += xv.w * kv.w;
        }
    }
    acc.x *= sigmoidf_(acc.x);
    acc.y *= sigmoidf_(acc.y);
    acc.z *= sigmoidf_(acc.z);
    acc.w *= sigmoidf_(acc.w);
    *(float4*)&g_xc[(long)row * D_INNER + d] = acc;
}

// ---------------------------------------------------------------------------
// A = -exp(A_log)
// ---------------------------------------------------------------------------
__global__ void aneg_kernel(const float* __restrict__ A_log)
{
    int i = blockIdx.x * blockDim.x + threadIdx.x;
    if (i < D_INNER * D_STATE) g_Aneg[i] = -__expf(A_log[i]);
}

// ---------------------------------------------------------------------------
// Selective scan, fused with output gating:
//   u[b,t,d] = (sum_n state_n(t) * C[t,n] + x[t,d]*D[d]) * silu(z[t,d])
// One 16-lane group per (b,d) scan; 2 scans/warp; 16 scans/block.
// Time is processed in SMEM-staged chunks of 64 to kill per-step LDG latency.
// ---------------------------------------------------------------------------
#define TCHUNK 64

__global__ __launch_bounds__(256)
void scan_kernel(const float* __restrict__ Dvec)
{
    __shared__ float sB [TCHUNK][D_STATE];
    __shared__ float sC [TCHUNK][D_STATE];
    __shared__ float sDl[TCHUNK][16];
    __shared__ float sX [TCHUNK][16];
    __shared__ float sZ [TCHUNK][16];

    const int tid = threadIdx.x;
    const int b = blockIdx.x >> 7;             // 128 blocks per batch
    const int d0 = (blockIdx.x & 127) * 16;
    const int warp = tid >> 5;
    const int half = (tid >> 4) & 1;
    const int n = tid & 15;                    // state index
    const int dl = warp * 2 + half;            // local scan id 0..15
    const int d = d0 + dl;

    const float An = g_Aneg[d * D_STATE + n];
    const float Dd = Dvec[d];
    float st = 0.0f;

    const long base_row = (long)b * SEQLEN;

    for (int c = 0; c < SEQLEN / TCHUNK; c++) {
        const int t0 = c * TCHUNK;
        __syncthreads();
#pragma unroll
        for (int r = 0; r < 4; r++) {
            int i = tid + r * 256;
            int tt = i >> 4, nn = i & 15;
            long row = base_row + t0 + tt;
            sB [tt][nn] = g_xdbl [row * XDBL_N + DT_RANK + nn];
            sC [tt][nn] = g_xdbl [row * XDBL_N + DT_RANK + D_STATE + nn];
            sDl[tt][nn] = g_delta[row * D_INNER + d0 + nn];
            sX [tt][nn] = g_xc   [row * D_INNER + d0 + nn];
            sZ [tt][nn] = g_zs   [row * D_INNER + d0 + nn];
        }
        __syncthreads();

#pragma unroll 4
        for (int tt = 0; tt < TCHUNK; tt++) {
            float dv = sDl[tt][dl];
            float xv = sX[tt][dl];
            float bv = sB[tt][n];
            float cv = sC[tt][n];
            float dA = __expf(dv * An);
            st = __fmaf_rn(dA, st, dv * xv * bv);
            float p = st * cv;
            p += __shfl_xor_sync(0xffffffffu, p, 1, 16);
            p += __shfl_xor_sync(0xffffffffu, p, 2, 16);
            p += __shfl_xor_sync(0xffffffffu, p, 4, 16);
            p += __shfl_xor_sync(0xffffffffu, p, 8, 16);
            if (n == 0) {
                long row = base_row + t0 + tt;
                g_u[row * D_INNER + d] = (p + xv * Dd) * sZ[tt][dl];
            }
        }
    }
}

// ---------------------------------------------------------------------------
// Host launcher
// ---------------------------------------------------------------------------
extern "C" void kernel_launch(void* const* d_in, const int* in_sizes, int n_in,
                              void* d_out, int out_size)
{
    const float* hidden = (const float*)d_in[0];   // [2,2048,1024]
    const float* W_in   = (const float*)d_in[1];   // [1024,4096]
    const float* ck     = (const float*)d_in[2];   // [4,1,2048]
    const float* cb     = (const float*)d_in[3];   // [2048]
    const float* W_x    = (const float*)d_in[4];   // [2048,96]
    const float* W_dt   = (const float*)d_in[5];   // [64,2048]
    const float* b_dt   = (const float*)d_in[6];   // [2048]
    const float* A_log  = (const float*)d_in[7];   // [2048,16]
    const float* Dvec   = (const float*)d_in[8];   // [2048]
    const float* W_out  = (const float*)d_in[9];   // [2048,1024]
    float* out = (float*)d_out;                    // [2,2048,1024]

    void *p_xraw, *p_zs, *p_xc, *p_xdbl, *p_delta, *p_u;
    cudaGetSymbolAddress(&p_xraw,  g_xraw);
    cudaGetSymbolAddress(&p_zs,    g_zs);
    cudaGetSymbolAddress(&p_xc,    g_xc);
    cudaGetSymbolAddress(&p_xdbl,  g_xdbl);
    cudaGetSymbolAddress(&p_delta, g_delta);
    cudaGetSymbolAddress(&p_u,     g_u);

    // 1) xz = hidden @ W_in ; split into x_raw / silu(z)
    {
        dim3 grid((2 * D_INNER) / BN, MROWS / BM);
        gemm_kernel<1><<<grid, 256>>>(hidden, W_in,
                                      (float*)p_xraw, (float*)p_zs, nullptr,
                                      MROWS, 2 * D_INNER, D_MODEL,
                                      D_MODEL, 2 * D_INNER, 2 * D_INNER);
    }
    // 2) depthwise conv + bias + silu
    {
        int threads = MROWS * (D_INNER / 4);
        conv_silu_kernel<<<(threads + 255) / 256, 256>>>(ck, cb);
    }
    // 3) x_dbl = xc @ W_x   (N = 96)
    {
        dim3 grid(1, MROWS / BM);
        gemm_kernel<0><<<grid, 256>>>((const float*)p_xc, W_x,
                                      (float*)p_xdbl, nullptr, nullptr,
                                      MROWS, XDBL_N, D_INNER,
                                      D_INNER, XDBL_N, XDBL_N);
    }
    // 4) delta = softplus(x_dbl[:, :64] @ W_dt + b_dt)
    {
        dim3 grid(D_INNER / BN, MROWS / BM);
        gemm_kernel<2><<<grid, 256>>>((const float*)p_xdbl, W_dt,
                                      (float*)p_delta, nullptr, b_dt,
                                      MROWS, D_INNER, DT_RANK,
                                      XDBL_N, D_INNER, D_INNER);
    }
    // 5) A = -exp(A_log)
    aneg_kernel<<<(D_INNER * D_STATE + 255) / 256, 256>>>(A_log);

    // 6) selective scan + gating -> u
    scan_kernel<<<(BATCH * D_INNER) / 16, 256>>>(Dvec);

    // 7) out = u @ W_out
    {
        dim3 grid(D_MODEL / BN, MROWS / BM);
        gemm_kernel<0><<<grid, 256>>>((const float*)p_u, W_out,
                                      out, nullptr, nullptr,
                                      MROWS, D_MODEL, D_INNER,
                                      D_INNER, D_MODEL, D_MODEL);
    }
}

// round 8
// speedup vs baseline: 1.6588x; 1.6588x over previous
#include <cuda_runtime.h>
#include <cuda_bf16.h>

// ---------------------------------------------------------------------------
// Problem constants
// ---------------------------------------------------------------------------
#define D_MODEL  1024
#define D_INNER  2048
#define D_STATE  16
#define D_CONV   4
#define DT_RANK  64
#define BATCH    2
#define SEQLEN   2048
#define MROWS    (BATCH * SEQLEN)         // 4096
#define XDBL_N   (DT_RANK + 2 * D_STATE)  // 96

// ---------------------------------------------------------------------------
// Scratch (static device globals; no allocation allowed)
// ---------------------------------------------------------------------------
__device__ float g_xraw [MROWS * D_INNER];
__device__ float g_zs   [MROWS * D_INNER];
__device__ float g_xc   [MROWS * D_INNER];
__device__ float g_xdbl [MROWS * XDBL_N];
__device__ float g_delta[MROWS * D_INNER];
__device__ float g_u    [MROWS * D_INNER];
__device__ float g_Aneg [D_INNER * D_STATE];

// bf16 hi/lo, transposed ([N][K]) weight buffers
__device__ __nv_bfloat16 g_WinT_h [4096 * 1024];
__device__ __nv_bfloat16 g_WinT_l [4096 * 1024];
__device__ __nv_bfloat16 g_WxT_h  [96 * 2048];
__device__ __nv_bfloat16 g_WxT_l  [96 * 2048];
__device__ __nv_bfloat16 g_WdtT_h [2048 * 64];
__device__ __nv_bfloat16 g_WdtT_l [2048 * 64];
__device__ __nv_bfloat16 g_WoutT_h[1024 * 2048];
__device__ __nv_bfloat16 g_WoutT_l[1024 * 2048];

__device__ __forceinline__ float sigmoidf_(float v) {
    return 1.0f / (1.0f + __expf(-v));
}

__device__ __forceinline__ unsigned smem_u32(const void* p) {
    unsigned a;
    asm("{ .reg .u64 t; cvta.to.shared.u64 t, %1; cvt.u32.u64 %0, t; }"
        : "=r"(a) : "l"(p));
    return a;
}

// pack two floats -> bf16x2 (lo half = first arg, at lower address)
__device__ __forceinline__ unsigned pkbf(float a, float b) {
    __nv_bfloat162 p = __floats2bfloat162_rn(a, b);
    return *reinterpret_cast<unsigned*>(&p);
}
__device__ __forceinline__ float resid(float v) {
    return v - __bfloat162float(__float2bfloat16(v));
}

#define LDSM4(r, addr)                                                        \
    asm volatile("ldmatrix.sync.aligned.m8n8.x4.shared.b16 {%0,%1,%2,%3}, [%4];" \
        : "=r"((r)[0]), "=r"((r)[1]), "=r"((r)[2]), "=r"((r)[3]) : "r"(addr))

#define MMA16816(c, a, b0, b1)                                                \
    asm volatile("mma.sync.aligned.m16n8k16.row.col.f32.bf16.bf16.f32 "       \
        "{%0,%1,%2,%3}, {%4,%5,%6,%7}, {%8,%9}, {%0,%1,%2,%3};"               \
        : "+f"((c)[0]), "+f"((c)[1]), "+f"((c)[2]), "+f"((c)[3])              \
        : "r"((a)[0]), "r"((a)[1]), "r"((a)[2]), "r"((a)[3]), "r"(b0), "r"(b1))

// ---------------------------------------------------------------------------
// Weight prep: W[K][N] fp32 -> transposed bf16 hi/lo [N][K]
// ---------------------------------------------------------------------------
__global__ void prep_w(const float* __restrict__ W,
                       __nv_bfloat16* __restrict__ hT,
                       __nv_bfloat16* __restrict__ lT, int K, int N)
{
    __shared__ float t[32][33];
    int k0 = blockIdx.x * 32, n0 = blockIdx.y * 32;
    int tx = threadIdx.x, ty = threadIdx.y;   // 32 x 8
#pragma unroll
    for (int i = 0; i < 4; i++) {
        int k = k0 + ty + i * 8;
        t[ty + i * 8][tx] = (k < K && n0 + tx < N) ? W[(size_t)k * N + n0 + tx] : 0.f;
    }
    __syncthreads();
#pragma unroll
    for (int i = 0; i < 4; i++) {
        int n = n0 + ty + i * 8, k = k0 + tx;
        if (n < N && k < K) {
            float v = t[tx][ty + i * 8];
            __nv_bfloat16 h = __float2bfloat16(v);
            hT[(size_t)n * K + k] = h;
            lT[(size_t)n * K + k] = __float2bfloat16(v - __bfloat162float(h));
        }
    }
}

// ---------------------------------------------------------------------------
// bf16 split-precision warp-MMA GEMM: C[M,N] = A[M,K] @ B[K,N]
// A fp32 (split in-loop); B pre-split/transposed bf16 [N][K].
// CTA tile 128x128, BK=32, 8 warps of 64x32, m16n8k16 HMMA.
// EPI 0: plain (col-guarded)   EPI 1: xz split + silu   EPI 2: bias+softplus
// ---------------------------------------------------------------------------
#define APITCH 80   // bytes per smem row (40 halves): 5r mod 8 -> LDSM conflict-free

template <int EPI>
__global__ __launch_bounds__(256, 2)
void mma_gemm(const float* __restrict__ A,
              const __nv_bfloat16* __restrict__ BTh,
              const __nv_bfloat16* __restrict__ BTl,
              float* __restrict__ C0, float* __restrict__ C1,
              const float* __restrict__ bias,
              int M, int N, int K, int lda, int ldc)
{
    __shared__ __align__(16) char sm[4 * 10240];
    char* sAh = sm;
    char* sAl = sm + 10240;
    char* sBh = sm + 20480;
    char* sBl = sm + 30720;

    const int tid = threadIdx.x, lane = tid & 31, wid = tid >> 5;
    const int row0 = blockIdx.y * 128, col0 = blockIdx.x * 128;
    const int wm = (wid >> 2) * 64, wn = (wid & 3) * 32;

    const int lrow = tid >> 1;          // 0..127
    const int kb = (tid & 1) * 16;      // k offset (halves) within 32-chunk

    float acc[4][4][4];
#pragma unroll
    for (int i = 0; i < 4; i++)
#pragma unroll
        for (int j = 0; j < 4; j++)
#pragma unroll
            for (int q = 0; q < 4; q++) acc[i][j][q] = 0.f;

    const unsigned smb = smem_u32(sm);
    const unsigned aHi = smb + (wm + (lane & 15)) * APITCH + (lane >> 4) * 16;
    const unsigned bHi = smb + 20480 + (wn + (lane & 15)) * APITCH + (lane >> 4) * 16;

    for (int k0 = 0; k0 < K; k0 += 32) {
        __syncthreads();
        // ---- A: fp32 -> bf16 hi/lo, [m][k] pitch-80 (16 halves/thread) ----
        {
            const float* ap = A + (size_t)(row0 + lrow) * lda + k0 + kb;
            float4 v0 = *(const float4*)(ap + 0);
            float4 v1 = *(const float4*)(ap + 4);
            float4 v2 = *(const float4*)(ap + 8);
            float4 v3 = *(const float4*)(ap + 12);
            uint4 h0 = make_uint4(pkbf(v0.x, v0.y), pkbf(v0.z, v0.w),
                                  pkbf(v1.x, v1.y), pkbf(v1.z, v1.w));
            uint4 h1 = make_uint4(pkbf(v2.x, v2.y), pkbf(v2.z, v2.w),
                                  pkbf(v3.x, v3.y), pkbf(v3.z, v3.w));
            uint4 l0 = make_uint4(pkbf(resid(v0.x), resid(v0.y)), pkbf(resid(v0.z), resid(v0.w)),
                                  pkbf(resid(v1.x), resid(v1.y)), pkbf(resid(v1.z), resid(v1.w)));
            uint4 l1 = make_uint4(pkbf(resid(v2.x), resid(v2.y)), pkbf(resid(v2.z), resid(v2.w)),
                                  pkbf(resid(v3.x), resid(v3.y)), pkbf(resid(v3.z), resid(v3.w)));
            char* da = sAh + lrow * APITCH + kb * 2;
            *(uint4*)(da) = h0;
            *(uint4*)(da + 16) = h1;
            char* dl = sAl + lrow * APITCH + kb * 2;
            *(uint4*)(dl) = l0;
            *(uint4*)(dl + 16) = l1;
        }
        // ---- B: pre-split bf16 [n][k] -> smem, 16 halves/thread (BUGFIX:
        //      was 8 halves -> half of every smem row was garbage -> NaN) ----
        {
            int gn = col0 + lrow;
            uint4 vh0 = make_uint4(0u, 0u, 0u, 0u), vh1 = vh0;
            uint4 vl0 = vh0, vl1 = vh0;
            if (gn < N) {
                const __nv_bfloat16* bph = BTh + (size_t)gn * K + k0 + kb;
                const __nv_bfloat16* bpl = BTl + (size_t)gn * K + k0 + kb;
                vh0 = *(const uint4*)(bph);
                vh1 = *(const uint4*)(bph + 8);
                vl0 = *(const uint4*)(bpl);
                vl1 = *(const uint4*)(bpl + 8);
            }
            char* db = sBh + lrow * APITCH + kb * 2;
            *(uint4*)(db) = vh0;
            *(uint4*)(db + 16) = vh1;
            char* dbl_ = sBl + lrow * APITCH + kb * 2;
            *(uint4*)(dbl_) = vl0;
            *(uint4*)(dbl_ + 16) = vl1;
        }
        __syncthreads();

        // ---- compute: 2 k16 steps ----
#pragma unroll
        for (int ks = 0; ks < 2; ks++) {
            const unsigned koff = ks * 32;
            unsigned ah[4][4], al[4][4], bh[2][4], bl[2][4];
#pragma unroll
            for (int mt = 0; mt < 4; mt++) {
                LDSM4(ah[mt], aHi + mt * (16 * APITCH) + koff);
                LDSM4(al[mt], aHi + 10240 + mt * (16 * APITCH) + koff);
            }
#pragma unroll
            for (int g = 0; g < 2; g++) {
                LDSM4(bh[g], bHi + g * (16 * APITCH) + koff);
                LDSM4(bl[g], bHi + 10240 + g * (16 * APITCH) + koff);
            }
#pragma unroll
            for (int mt = 0; mt < 4; mt++)
#pragma unroll
                for (int nt = 0; nt < 4; nt++) {
                    const int g = nt >> 1, o = nt & 1;
                    MMA16816(acc[mt][nt], ah[mt], bh[g][o], bh[g][2 + o]);
                    MMA16816(acc[mt][nt], ah[mt], bl[g][o], bl[g][2 + o]);
                    MMA16816(acc[mt][nt], al[mt], bh[g][o], bh[g][2 + o]);
                }
        }
    }

    // ---- epilogue: fragment -> global ----
    const int g = lane >> 2, tg = (lane & 3) * 2;
#pragma unroll
    for (int mt = 0; mt < 4; mt++) {
#pragma unroll
        for (int nt = 0; nt < 4; nt++) {
            float* c = acc[mt][nt];
            int r0 = row0 + wm + mt * 16 + g;
            int r1 = r0 + 8;
            int cc = col0 + wn + nt * 8 + tg;
            if (EPI == 0) {
                if (cc < N) {
                    *(float2*)&C0[(size_t)r0 * ldc + cc] = make_float2(c[0], c[1]);
                    *(float2*)&C0[(size_t)r1 * ldc + cc] = make_float2(c[2], c[3]);
                }
            } else if (EPI == 1) {
                int h = cc >> 1;   // even col -> x, odd col -> z
                C0[(size_t)r0 * D_INNER + h] = c[0];
                C1[(size_t)r0 * D_INNER + h] = c[1] * sigmoidf_(c[1]);
                C0[(size_t)r1 * D_INNER + h] = c[2];
                C1[(size_t)r1 * D_INNER + h] = c[3] * sigmoidf_(c[3]);
            } else {
                float b0v = bias[cc], b1v = bias[cc + 1];
                float a0 = c[0] + b0v, a1 = c[1] + b1v;
                float a2 = c[2] + b0v, a3 = c[3] + b1v;
                a0 = (a0 > 20.f) ? a0 : log1pf(__expf(a0));
                a1 = (a1 > 20.f) ? a1 : log1pf(__expf(a1));
                a2 = (a2 > 20.f) ? a2 : log1pf(__expf(a2));
                a3 = (a3 > 20.f) ? a3 : log1pf(__expf(a3));
                *(float2*)&C0[(size_t)r0 * ldc + cc] = make_float2(a0, a1);
                *(float2*)&C0[(size_t)r1 * ldc + cc] = make_float2(a2, a3);
            }
        }
    }
}

// ---------------------------------------------------------------------------
// Depthwise conv (SAME pad lo=1 hi=2) + bias + silu
// ---------------------------------------------------------------------------
__global__ void conv_silu_kernel(const float* __restrict__ ck,
                                 const float* __restrict__ cb)
{
    int idx = blockIdx.x * blockDim.x + threadIdx.x;
    if (idx >= MROWS * (D_INNER / 4)) return;
    int row = idx >> 9;
    int d = (idx & 511) << 2;
    int b = row >> 11;
    int l = row & (SEQLEN - 1);

    float4 acc = *(const float4*)&cb[d];
#pragma unroll
    for (int w = 0; w < D_CONV; w++) {
        int ls = l + w - 1;
        if (ls >= 0 && ls < SEQLEN) {
            float4 xv = *(const float4*)&g_xraw[((size_t)(b * SEQLEN + ls)) * D_INNER + d];
            float4 kv = *(const float4*)&ck[w * D_INNER + d];
            acc.x += xv.x * kv.x; acc.y += xv.y * kv.y;
            acc.z += xv.z * kv.z; acc.w += xv.w * kv.w;
        }
    }
    acc.x *= sigmoidf_(acc.x); acc.y *= sigmoidf_(acc.y);
    acc.z *= sigmoidf_(acc.z); acc.w *= sigmoidf_(acc.w);
    *(float4*)&g_xc[(size_t)row * D_INNER + d] = acc;
}

__global__ void aneg_kernel(const float* __restrict__ A_log)
{
    int i = blockIdx.x * blockDim.x + threadIdx.x;
    if (i < D_INNER * D_STATE) g_Aneg[i] = -__expf(A_log[i]);
}

// ---------------------------------------------------------------------------
// Selective scan fused with gating (unchanged from passing R3 kernel)
// ---------------------------------------------------------------------------
#define TCHUNK 64

__global__ __launch_bounds__(256)
void scan_kernel(const float* __restrict__ Dvec)
{
    __shared__ float sB [TCHUNK][D_STATE];
    __shared__ float sC [TCHUNK][D_STATE];
    __shared__ float sDl[TCHUNK][16];
    __shared__ float sX [TCHUNK][16];
    __shared__ float sZ [TCHUNK][16];

    const int tid = threadIdx.x;
    const int b = blockIdx.x >> 7;
    const int d0 = (blockIdx.x & 127) * 16;
    const int warp = tid >> 5;
    const int half = (tid >> 4) & 1;
    const int n = tid & 15;
    const int dl = warp * 2 + half;
    const int d = d0 + dl;

    const float An = g_Aneg[d * D_STATE + n];
    const float Dd = Dvec[d];
    float st = 0.0f;
    const long base_row = (long)b * SEQLEN;

    for (int c = 0; c < SEQLEN / TCHUNK; c++) {
        const int t0 = c * TCHUNK;
        __syncthreads();
#pragma unroll
        for (int r = 0; r < 4; r++) {
            int i = tid + r * 256;
            int tt = i >> 4, nn = i & 15;
            long row = base_row + t0 + tt;
            sB [tt][nn] = g_xdbl [row * XDBL_N + DT_RANK + nn];
            sC [tt][nn] = g_xdbl [row * XDBL_N + DT_RANK + D_STATE + nn];
            sDl[tt][nn] = g_delta[row * D_INNER + d0 + nn];
            sX [tt][nn] = g_xc   [row * D_INNER + d0 + nn];
            sZ [tt][nn] = g_zs   [row * D_INNER + d0 + nn];
        }
        __syncthreads();

#pragma unroll 4
        for (int tt = 0; tt < TCHUNK; tt++) {
            float dv = sDl[tt][dl];
            float xv = sX[tt][dl];
            float bv = sB[tt][n];
            float cv = sC[tt][n];
            float dA = __expf(dv * An);
            st = __fmaf_rn(dA, st, dv * xv * bv);
            float p = st * cv;
            p += __shfl_xor_sync(0xffffffffu, p, 1, 16);
            p += __shfl_xor_sync(0xffffffffu, p, 2, 16);
            p += __shfl_xor_sync(0xffffffffu, p, 4, 16);
            p += __shfl_xor_sync(0xffffffffu, p, 8, 16);
            if (n == 0) {
                long row = base_row + t0 + tt;
                g_u[row * D_INNER + d] = (p + xv * Dd) * sZ[tt][dl];
            }
        }
    }
}

// ---------------------------------------------------------------------------
// Host launcher
// ---------------------------------------------------------------------------
extern "C" void kernel_launch(void* const* d_in, const int* in_sizes, int n_in,
                              void* d_out, int out_size)
{
    const float* hidden = (const float*)d_in[0];
    const float* W_in   = (const float*)d_in[1];
    const float* ck     = (const float*)d_in[2];
    const float* cb     = (const float*)d_in[3];
    const float* W_x    = (const float*)d_in[4];
    const float* W_dt   = (const float*)d_in[5];
    const float* b_dt   = (const float*)d_in[6];
    const float* A_log  = (const float*)d_in[7];
    const float* Dvec   = (const float*)d_in[8];
    const float* W_out  = (const float*)d_in[9];
    float* out = (float*)d_out;

    void *p_xraw, *p_zs, *p_xc, *p_xdbl, *p_delta, *p_u;
    cudaGetSymbolAddress(&p_xraw,  g_xraw);
    cudaGetSymbolAddress(&p_zs,    g_zs);
    cudaGetSymbolAddress(&p_xc,    g_xc);
    cudaGetSymbolAddress(&p_xdbl,  g_xdbl);
    cudaGetSymbolAddress(&p_delta, g_delta);
    cudaGetSymbolAddress(&p_u,     g_u);

    void *p_winh, *p_winl, *p_wxh, *p_wxl, *p_wdth, *p_wdtl, *p_wouth, *p_woutl;
    cudaGetSymbolAddress(&p_winh,  g_WinT_h);  cudaGetSymbolAddress(&p_winl,  g_WinT_l);
    cudaGetSymbolAddress(&p_wxh,   g_WxT_h);   cudaGetSymbolAddress(&p_wxl,   g_WxT_l);
    cudaGetSymbolAddress(&p_wdth,  g_WdtT_h);  cudaGetSymbolAddress(&p_wdtl,  g_WdtT_l);
    cudaGetSymbolAddress(&p_wouth, g_WoutT_h); cudaGetSymbolAddress(&p_woutl, g_WoutT_l);

    dim3 tb(32, 8);
    // 0) weight prep: transpose + bf16 hi/lo split
    prep_w<<<dim3(D_MODEL / 32, (2 * D_INNER) / 32), tb>>>(W_in,
        (__nv_bfloat16*)p_winh, (__nv_bfloat16*)p_winl, D_MODEL, 2 * D_INNER);
    prep_w<<<dim3(D_INNER / 32, 3), tb>>>(W_x,
        (__nv_bfloat16*)p_wxh, (__nv_bfloat16*)p_wxl, D_INNER, XDBL_N);
    prep_w<<<dim3(DT_RANK / 32, D_INNER / 32), tb>>>(W_dt,
        (__nv_bfloat16*)p_wdth, (__nv_bfloat16*)p_wdtl, DT_RANK, D_INNER);
    prep_w<<<dim3(D_INNER / 32, D_MODEL / 32), tb>>>(W_out,
        (__nv_bfloat16*)p_wouth, (__nv_bfloat16*)p_woutl, D_INNER, D_MODEL);

    // 5) A = -exp(A_log)  (independent; launch early)
    aneg_kernel<<<(D_INNER * D_STATE + 255) / 256, 256>>>(A_log);

    // 1) xz = hidden @ W_in ; split into x_raw / silu(z)
    {
        dim3 grid((2 * D_INNER) / 128, MROWS / 128);
        mma_gemm<1><<<grid, 256>>>(hidden,
            (const __nv_bfloat16*)p_winh, (const __nv_bfloat16*)p_winl,
            (float*)p_xraw, (float*)p_zs, nullptr,
            MROWS, 2 * D_INNER, D_MODEL, D_MODEL, 2 * D_INNER);
    }
    // 2) depthwise conv + bias + silu
    {
        int threads = MROWS * (D_INNER / 4);
        conv_silu_kernel<<<(threads + 255) / 256, 256>>>(ck, cb);
    }
    // 3) x_dbl = xc @ W_x (N=96 inside one 128 tile)
    {
        dim3 grid(1, MROWS / 128);
        mma_gemm<0><<<grid, 256>>>((const float*)p_xc,
            (const __nv_bfloat16*)p_wxh, (const __nv_bfloat16*)p_wxl,
            (float*)p_xdbl, nullptr, nullptr,
            MROWS, XDBL_N, D_INNER, D_INNER, XDBL_N);
    }
    // 4) delta = softplus(x_dbl[:, :64] @ W_dt + b_dt)
    {
        dim3 grid(D_INNER / 128, MROWS / 128);
        mma_gemm<2><<<grid, 256>>>((const float*)p_xdbl,
            (const __nv_bfloat16*)p_wdth, (const __nv_bfloat16*)p_wdtl,
            (float*)p_delta, nullptr, b_dt,
            MROWS, D_INNER, DT_RANK, XDBL_N, D_INNER);
    }
    // 6) selective scan + gating -> u
    scan_kernel<<<(BATCH * D_INNER) / 16, 256>>>(Dvec);

    // 7) out = u @ W_out
    {
        dim3 grid(D_MODEL / 128, MROWS / 128);
        mma_gemm<0><<<grid, 256>>>((const float*)p_u,
            (const __nv_bfloat16*)p_wouth, (const __nv_bfloat16*)p_woutl,
            out, nullptr, nullptr,
            MROWS, D_MODEL, D_INNER, D_INNER, D_MODEL);
    }
}